// round 1
// baseline (speedup 1.0000x reference)
#include <cuda_runtime.h>
#include <cuda_bf16.h>

#define NB 8
#define NL 2048
#define NE 256
#define NH 4
#define ND 64

// ---------------- scratch (device globals; no allocation allowed) -----------
__device__ float g_QK[(size_t)NB * NL * 2 * NE];   // [B*L, 512]  (q | k)   32 MB
__device__ float g_S [(size_t)NB * NH * NL * NL];  // [32, 2048, 2048]     536 MB
__device__ float g_Bm[(size_t)NB * NL * NL];       // [8, 2048, 2048]      134 MB
__device__ float g_AG[(size_t)NB * NL * NE];       // [B*L, 256]            16 MB

// ---------------------------------------------------------------------------
// Generic tiled SGEMM:  C = alpha * A * op(B) (+ bias)
//   A: [M,K] row-major (lda); op(B)=B^T if TRANS_B (B is [N,K]), else B [K,N]
//   Batched via blockIdx.z with two-level offsets:
//     z -> zo = z/inner, zi = z%inner ; A += zo*sAo + zi*sAi (same for B)
//     C += z * sCo
//   Tile 128x128, Ktile 8, 256 threads, 8x8 per thread. All dims assumed
//   divisible (true for every call here).
// ---------------------------------------------------------------------------
template <bool TRANS_B, bool HAS_BIAS>
__global__ __launch_bounds__(256, 2)
void gemm128(const float* __restrict__ A, int lda, long sAo, long sAi,
             const float* __restrict__ Bm, int ldb, long sBo, long sBi,
             float* __restrict__ C, int ldc, long sCo,
             int inner, int K, float alpha, const float* __restrict__ bias)
{
    __shared__ float As[8][132];
    __shared__ float Bs[8][132];

    const int z  = blockIdx.z;
    const int zo = z / inner;
    const int zi = z - zo * inner;
    A  += (long)zo * sAo + (long)zi * sAi;
    Bm += (long)zo * sBo + (long)zi * sBi;
    C  += (long)z * sCo;

    const int tid  = threadIdx.x;
    const int tx   = tid & 15;       // 0..15 -> col group
    const int ty   = tid >> 4;       // 0..15 -> row group
    const int row0 = blockIdx.y * 128;
    const int col0 = blockIdx.x * 128;

    const int lr = tid >> 1;         // 0..127
    const int lk = (tid & 1) * 4;    // 0 or 4

    float acc[8][8];
#pragma unroll
    for (int i = 0; i < 8; i++)
#pragma unroll
        for (int j = 0; j < 8; j++) acc[i][j] = 0.f;

    const float* Aptr = A + (long)(row0 + lr) * lda + lk;

    for (int k0 = 0; k0 < K; k0 += 8) {
        // --- load A tile [128 x 8], transposed into As[k][row] ---
        {
            float4 v = *(const float4*)(Aptr + k0);
            As[lk + 0][lr] = v.x; As[lk + 1][lr] = v.y;
            As[lk + 2][lr] = v.z; As[lk + 3][lr] = v.w;
        }
        // --- load B tile into Bs[k][col] ---
        if (TRANS_B) {
            float4 v = *(const float4*)(Bm + (long)(col0 + lr) * ldb + k0 + lk);
            Bs[lk + 0][lr] = v.x; Bs[lk + 1][lr] = v.y;
            Bs[lk + 2][lr] = v.z; Bs[lk + 3][lr] = v.w;
        } else {
            const int bk = tid >> 5;          // 0..7
            const int bc = (tid & 31) * 4;    // 0..124
            float4 v = *(const float4*)(Bm + (long)(k0 + bk) * ldb + col0 + bc);
            *(float4*)&Bs[bk][bc] = v;
        }
        __syncthreads();

#pragma unroll
        for (int kk = 0; kk < 8; kk++) {
            float4 a0 = *(const float4*)&As[kk][ty * 8];
            float4 a1 = *(const float4*)&As[kk][ty * 8 + 4];
            float4 b0 = *(const float4*)&Bs[kk][tx * 8];
            float4 b1 = *(const float4*)&Bs[kk][tx * 8 + 4];
            float a[8] = {a0.x, a0.y, a0.z, a0.w, a1.x, a1.y, a1.z, a1.w};
            float b[8] = {b0.x, b0.y, b0.z, b0.w, b1.x, b1.y, b1.z, b1.w};
#pragma unroll
            for (int i = 0; i < 8; i++)
#pragma unroll
                for (int j = 0; j < 8; j++)
                    acc[i][j] += a[i] * b[j];
        }
        __syncthreads();
    }

    // --- epilogue ---
#pragma unroll
    for (int i = 0; i < 8; i++) {
        const long r = row0 + ty * 8 + i;
#pragma unroll
        for (int j = 0; j < 8; j += 4) {
            const int c = col0 + tx * 8 + j;
            float4 v;
            v.x = acc[i][j + 0] * alpha;
            v.y = acc[i][j + 1] * alpha;
            v.z = acc[i][j + 2] * alpha;
            v.w = acc[i][j + 3] * alpha;
            if (HAS_BIAS) {
                v.x += bias[c + 0]; v.y += bias[c + 1];
                v.z += bias[c + 2]; v.w += bias[c + 3];
            }
            *(float4*)(C + r * ldc + c) = v;
        }
    }
}

// ---------------------------------------------------------------------------
// Per-row softmax over each head's score row, then mean over the 4 heads.
// One block per (batch, query-row). 256 threads; each thread owns 8 columns.
// ---------------------------------------------------------------------------
__device__ __forceinline__ float warp_max(float v) {
#pragma unroll
    for (int o = 16; o; o >>= 1) v = fmaxf(v, __shfl_xor_sync(0xffffffffu, v, o));
    return v;
}
__device__ __forceinline__ float warp_sum(float v) {
#pragma unroll
    for (int o = 16; o; o >>= 1) v += __shfl_xor_sync(0xffffffffu, v, o);
    return v;
}

__global__ __launch_bounds__(256)
void softmax_mean_kernel(const float* __restrict__ S, float* __restrict__ Bm)
{
    __shared__ float red[8];
    const int bi   = blockIdx.x;          // b*2048 + i
    const int b    = bi >> 11;
    const int i    = bi & 2047;
    const int tid  = threadIdx.x;
    const int wid  = tid >> 5;
    const int lane = tid & 31;

    float acc[8] = {0, 0, 0, 0, 0, 0, 0, 0};

    for (int h = 0; h < NH; h++) {
        const float* row = S + (((long)(b * NH + h)) * NL + i) * NL;
        float v[8];
#pragma unroll
        for (int j = 0; j < 8; j++) v[j] = row[tid + j * 256];

        // row max
        float m = v[0];
#pragma unroll
        for (int j = 1; j < 8; j++) m = fmaxf(m, v[j]);
        m = warp_max(m);
        if (lane == 0) red[wid] = m;
        __syncthreads();
        float m2 = red[0];
#pragma unroll
        for (int w = 1; w < 8; w++) m2 = fmaxf(m2, red[w]);

        // exp + row sum
        float s = 0.f;
#pragma unroll
        for (int j = 0; j < 8; j++) { v[j] = __expf(v[j] - m2); s += v[j]; }
        s = warp_sum(s);
        __syncthreads();                 // all reads of red (max) done
        if (lane == 0) red[wid] = s;
        __syncthreads();
        float st = red[0];
#pragma unroll
        for (int w = 1; w < 8; w++) st += red[w];

        const float inv = 0.25f / st;    // 1/(H * sum)
#pragma unroll
        for (int j = 0; j < 8; j++) acc[j] += v[j] * inv;
        __syncthreads();                 // red reuse next head
    }

    float* o = Bm + (long)bi * NL;
#pragma unroll
    for (int j = 0; j < 8; j++) o[tid + j * 256] = acc[j];
}

// ---------------------------------------------------------------------------
extern "C" void kernel_launch(void* const* d_in, const int* in_sizes, int n_in,
                              void* d_out, int out_size)
{
    (void)in_sizes; (void)n_in; (void)out_size;
    const float* x   = (const float*)d_in[0];  // [B, L, E]
    const float* w   = (const float*)d_in[1];  // [3E, E]
    const float* bia = (const float*)d_in[2];  // [3E]
    const float* Wg  = (const float*)d_in[3];  // [E, E]
    const float* Bg  = (const float*)d_in[4];  // [E]
    float* out = (float*)d_out;                // [B, L, E]

    float *QK, *S, *Bmat, *AGG;
    cudaGetSymbolAddress((void**)&QK,   g_QK);
    cudaGetSymbolAddress((void**)&S,    g_S);
    cudaGetSymbolAddress((void**)&Bmat, g_Bm);
    cudaGetSymbolAddress((void**)&AGG,  g_AG);

    // 1) QK[i, 0:512] = x @ W[0:512,:]^T + bias[0:512]   (q | k)
    {
        dim3 grid((2 * NE) / 128, (NB * NL) / 128, 1);
        gemm128<true, true><<<grid, 256>>>(
            x, NE, 0, 0,
            w, NE, 0, 0,
            QK, 2 * NE, 0,
            1, NE, 1.f, bia);
    }

    // 2) S[z=b*4+h] = (1/sqrt(D)) * q_h @ k_h^T
    {
        dim3 grid(NL / 128, NL / 128, NB * NH);
        gemm128<true, false><<<grid, 256>>>(
            QK,      2 * NE, (long)NL * 2 * NE, ND,
            QK + NE, 2 * NE, (long)NL * 2 * NE, ND,
            S, NL, (long)NL * NL,
            NH, ND, 0.125f, nullptr);
    }

    // 3) Bm[b,i,:] = mean_h softmax(S[b,h,i,:])
    softmax_mean_kernel<<<NB * NL, 256>>>(S, Bmat);

    // 4) AGG[b] = Bm[b] @ x[b]
    {
        dim3 grid(NE / 128, NL / 128, NB);
        gemm128<false, false><<<grid, 256>>>(
            Bmat, NL, (long)NL * NL, 0,
            x,    NE, (long)NL * NE, 0,
            AGG, NE, (long)NL * NE,
            1, NL, 1.f, nullptr);
    }

    // 5) out = AGG @ W_gnn + B_gnn
    {
        dim3 grid(NE / 128, (NB * NL) / 128, 1);
        gemm128<false, true><<<grid, 256>>>(
            AGG, NE, 0, 0,
            Wg,  NE, 0, 0,
            out, NE, 0,
            1, NE, 1.f, Bg);
    }
}

// round 3
// speedup vs baseline: 2.5684x; 2.5684x over previous
#include <cuda_runtime.h>
#include <cuda_bf16.h>
#include <cstdint>

#define NB 8
#define NL 2048
#define NE 256
#define NH 4
#define ND 64

// ---------------- scratch (device globals; no allocation allowed) -----------
__device__ float g_QK [(size_t)NB * NL * 2 * NE];   // [16384, 512]  (q | k)
__device__ float g_S  [(size_t)NB * NH * NL * NL];  // [32, 2048, 2048]
__device__ float g_Bm [(size_t)NB * NL * NL];       // [8, 2048, 2048]
__device__ float g_AG [(size_t)NB * NL * NE];       // [16384, 256]
__device__ float g_xT [(size_t)NB * NE * NL];       // [8][256][2048]
__device__ float g_WgT[(size_t)NE * NE];            // [256, 256]
__device__ float g_xr [(size_t)NB * NL * NE];       // tf32-rounded x
__device__ float g_wr [(size_t)2 * NE * NE];        // tf32-rounded w[0:512]

// ------------------------------- helpers ------------------------------------
__device__ __forceinline__ uint32_t smem_u32(const void* p) {
    uint32_t a;
    asm("{ .reg .u64 t; cvta.to.shared.u64 t, %1; cvt.u32.u64 %0, t; }"
        : "=r"(a) : "l"(p));
    return a;
}

__device__ __forceinline__ float rtf32(float x) {
    uint32_t u;
    asm("cvt.rna.tf32.f32 %0, %1;" : "=r"(u) : "f"(x));
    return __uint_as_float(u);
}

#define CP_ASYNC16(dst, src) \
    asm volatile("cp.async.cg.shared.global [%0], [%1], 16;" \
                 :: "r"(dst), "l"(src) : "memory")
#define CP_COMMIT() asm volatile("cp.async.commit_group;" ::: "memory")
#define CP_WAIT(n)  asm volatile("cp.async.wait_group %0;" :: "n"(n) : "memory")

#define MMA_TF32(d, a, b)                                                      \
    asm volatile("mma.sync.aligned.m16n8k8.row.col.f32.tf32.tf32.f32 "         \
        "{%0,%1,%2,%3}, {%4,%5,%6,%7}, {%8,%9}, {%0,%1,%2,%3};"                \
        : "+f"((d)[0]), "+f"((d)[1]), "+f"((d)[2]), "+f"((d)[3])               \
        : "r"((a)[0]), "r"((a)[1]), "r"((a)[2]), "r"((a)[3]),                  \
          "r"((b)[0]), "r"((b)[1]))

// ------------------------------- mma GEMM -----------------------------------
// C[z] = alpha * A_z * B_z^T (+ bias[col]).  A [M,K], B [N,K], both row-major
// (K-major).  Inputs must already be tf32-rounded fp32.
// CTA tile 128x128, K chunk 32, 8 warps (2x4), warp tile 64x32, cp.async
// double buffer.  smem rows padded to 36 floats (bank-conflict-free frags,
// 16B-aligned cp.async rows).
#define STG_FLOATS 9216            // per stage: A 128*36 + B 128*36
#define STG_BYTES  36864
#define GEMM_SMEM  (2 * STG_BYTES) // 73728

template <bool ROUND_OUT, bool HAS_BIAS>
__global__ __launch_bounds__(256, 2)
void mma_gemm(const float* __restrict__ A, int lda, int a_zo_row, int a_zi_col, int a_col_base,
              const float* __restrict__ Bp, int ldb, int b_zo_row, int b_zi_col, int b_col_base,
              float* __restrict__ C, int ldc, long sC,
              int inner, int nk, float alpha, const float* __restrict__ bias)
{
    extern __shared__ __align__(16) float smem[];
    const int tid    = threadIdx.x;
    const int warpId = tid >> 5;
    const int lane   = tid & 31;
    const int g  = lane >> 2;
    const int tg = lane & 3;
    const int wr = (warpId & 1) * 64;
    const int wc = (warpId >> 1) * 32;

    const int z  = blockIdx.z;
    const int zo = z / inner;
    const int zi = z - zo * inner;

    const float* Ag = A  + ((long)zo * a_zo_row + (long)blockIdx.y * 128) * lda
                         + a_col_base + zi * a_zi_col;
    const float* Bg = Bp + ((long)zo * b_zo_row + (long)blockIdx.x * 128) * ldb
                         + b_col_base + zi * b_zi_col;

    const uint32_t sbase = smem_u32(smem);

    // ---- stage loader: A tile [128 x 32] + B tile [128 x 32] ----
    auto load_stage = [&](int st, int kc) {
        const uint32_t da = sbase + st * STG_BYTES;
        const float* a = Ag + kc * 32;
        const float* b = Bg + kc * 32;
#pragma unroll
        for (int i = 0; i < 4; i++) {
            const int idx = tid + 256 * i;
            const int row = idx >> 3, c4 = idx & 7;
            CP_ASYNC16(da + row * 144 + c4 * 16, a + (long)row * lda + c4 * 4);
        }
#pragma unroll
        for (int i = 0; i < 4; i++) {
            const int idx = tid + 256 * i;
            const int row = idx >> 3, c4 = idx & 7;
            CP_ASYNC16(da + 18432 + row * 144 + c4 * 16, b + (long)row * ldb + c4 * 4);
        }
    };

    float acc[4][4][4];
#pragma unroll
    for (int m = 0; m < 4; m++)
#pragma unroll
        for (int n = 0; n < 4; n++)
#pragma unroll
            for (int c = 0; c < 4; c++) acc[m][n][c] = 0.f;

    load_stage(0, 0);
    CP_COMMIT();

    for (int i = 0; i < nk; i++) {
        if (i + 1 < nk) {
            load_stage((i + 1) & 1, i + 1);
            CP_COMMIT();
            CP_WAIT(1);
        } else {
            CP_WAIT(0);
        }
        __syncthreads();

        const uint32_t* As = (const uint32_t*)(smem + (i & 1) * STG_FLOATS);
        const uint32_t* Bs = As + 4608;

#pragma unroll
        for (int j = 0; j < 4; j++) {
            uint32_t af[4][4], bf[4][2];
#pragma unroll
            for (int mt = 0; mt < 4; mt++) {
                const int r0 = wr + mt * 16 + g;
                af[mt][0] = As[ r0      * 36 + j * 8 + tg    ];
                af[mt][1] = As[(r0 + 8) * 36 + j * 8 + tg    ];
                af[mt][2] = As[ r0      * 36 + j * 8 + tg + 4];
                af[mt][3] = As[(r0 + 8) * 36 + j * 8 + tg + 4];
            }
#pragma unroll
            for (int nt = 0; nt < 4; nt++) {
                const int r0 = wc + nt * 8 + g;
                bf[nt][0] = Bs[r0 * 36 + j * 8 + tg    ];
                bf[nt][1] = Bs[r0 * 36 + j * 8 + tg + 4];
            }
#pragma unroll
            for (int mt = 0; mt < 4; mt++)
#pragma unroll
                for (int nt = 0; nt < 4; nt++)
                    MMA_TF32(acc[mt][nt], af[mt], bf[nt]);
        }
        __syncthreads();
    }

    // ---- epilogue ----
    float* Cz = C + (long)z * sC;
    const long crow0 = (long)blockIdx.y * 128;
    const int  ccol0 = blockIdx.x * 128;

#pragma unroll
    for (int mt = 0; mt < 4; mt++) {
#pragma unroll
        for (int nt = 0; nt < 4; nt++) {
            const long r = crow0 + wr + mt * 16 + g;
            const int  c = ccol0 + wc + nt * 8 + tg * 2;
            float b0 = 0.f, b1 = 0.f;
            if (HAS_BIAS) { b0 = bias[c]; b1 = bias[c + 1]; }
            float v00 = acc[mt][nt][0] * alpha + b0;
            float v01 = acc[mt][nt][1] * alpha + b1;
            float v10 = acc[mt][nt][2] * alpha + b0;
            float v11 = acc[mt][nt][3] * alpha + b1;
            if (ROUND_OUT) {
                v00 = rtf32(v00); v01 = rtf32(v01);
                v10 = rtf32(v10); v11 = rtf32(v11);
            }
            *(float2*)(Cz +  r      * ldc + c) = make_float2(v00, v01);
            *(float2*)(Cz + (r + 8) * ldc + c) = make_float2(v10, v11);
        }
    }
}

// ---------------------------------------------------------------------------
// elementwise tf32 round-copy
__global__ void round_copy(const float4* __restrict__ in, float4* __restrict__ out, int n4)
{
    const int i = blockIdx.x * blockDim.x + threadIdx.x;
    if (i < n4) {
        float4 v = in[i];
        v.x = rtf32(v.x); v.y = rtf32(v.y); v.z = rtf32(v.z); v.w = rtf32(v.w);
        out[i] = v;
    }
}

// batched 32x32 tiled transpose with tf32 rounding: out[z][c][r] = rtf32(in[z][r][c])
__global__ void transpose_round(const float* __restrict__ in, float* __restrict__ out,
                                int R, int Cn)
{
    __shared__ float t[32][33];
    in  += (size_t)blockIdx.z * R * Cn;
    out += (size_t)blockIdx.z * R * Cn;
    const int r0 = blockIdx.y * 32, c0 = blockIdx.x * 32;
    const int x = threadIdx.x, y = threadIdx.y;
#pragma unroll
    for (int i = 0; i < 32; i += 8)
        t[y + i][x] = in[(long)(r0 + y + i) * Cn + c0 + x];
    __syncthreads();
#pragma unroll
    for (int i = 0; i < 32; i += 8)
        out[(long)(c0 + y + i) * R + r0 + x] = rtf32(t[x][y + i]);
}

// ---------------------------------------------------------------------------
__device__ __forceinline__ float warp_max(float v) {
#pragma unroll
    for (int o = 16; o; o >>= 1) v = fmaxf(v, __shfl_xor_sync(0xffffffffu, v, o));
    return v;
}
__device__ __forceinline__ float warp_sum(float v) {
#pragma unroll
    for (int o = 16; o; o >>= 1) v += __shfl_xor_sync(0xffffffffu, v, o);
    return v;
}

__global__ __launch_bounds__(256)
void softmax_mean_kernel(const float* __restrict__ S, float* __restrict__ Bm)
{
    __shared__ float red[8];
    const int bi   = blockIdx.x;
    const int b    = bi >> 11;
    const int i    = bi & 2047;
    const int tid  = threadIdx.x;
    const int wid  = tid >> 5;
    const int lane = tid & 31;

    float acc[8] = {0, 0, 0, 0, 0, 0, 0, 0};

    for (int h = 0; h < NH; h++) {
        const float* row = S + (((long)(b * NH + h)) * NL + i) * NL;
        float v[8];
#pragma unroll
        for (int j = 0; j < 8; j++) v[j] = row[tid + j * 256];

        float m = v[0];
#pragma unroll
        for (int j = 1; j < 8; j++) m = fmaxf(m, v[j]);
        m = warp_max(m);
        if (lane == 0) red[wid] = m;
        __syncthreads();
        float m2 = red[0];
#pragma unroll
        for (int w = 1; w < 8; w++) m2 = fmaxf(m2, red[w]);

        float s = 0.f;
#pragma unroll
        for (int j = 0; j < 8; j++) { v[j] = __expf(v[j] - m2); s += v[j]; }
        s = warp_sum(s);
        __syncthreads();
        if (lane == 0) red[wid] = s;
        __syncthreads();
        float st = red[0];
#pragma unroll
        for (int w = 1; w < 8; w++) st += red[w];

        const float inv = 0.25f / st;
#pragma unroll
        for (int j = 0; j < 8; j++) acc[j] += v[j] * inv;
        __syncthreads();
    }

    float* o = Bm + (long)bi * NL;
#pragma unroll
    for (int j = 0; j < 8; j++) o[tid + j * 256] = rtf32(acc[j]);
}

// ---------------------------------------------------------------------------
extern "C" void kernel_launch(void* const* d_in, const int* in_sizes, int n_in,
                              void* d_out, int out_size)
{
    (void)in_sizes; (void)n_in; (void)out_size;
    const float* x   = (const float*)d_in[0];
    const float* w   = (const float*)d_in[1];
    const float* bia = (const float*)d_in[2];
    const float* Wg  = (const float*)d_in[3];
    const float* Bg  = (const float*)d_in[4];
    float* out = (float*)d_out;

    float *QK, *S, *Bm, *AG, *xT, *WgT, *xr, *wr;
    cudaGetSymbolAddress((void**)&QK,  g_QK);
    cudaGetSymbolAddress((void**)&S,   g_S);
    cudaGetSymbolAddress((void**)&Bm,  g_Bm);
    cudaGetSymbolAddress((void**)&AG,  g_AG);
    cudaGetSymbolAddress((void**)&xT,  g_xT);
    cudaGetSymbolAddress((void**)&WgT, g_WgT);
    cudaGetSymbolAddress((void**)&xr,  g_xr);
    cudaGetSymbolAddress((void**)&wr,  g_wr);

    cudaFuncSetAttribute(mma_gemm<true,  true >, cudaFuncAttributeMaxDynamicSharedMemorySize, GEMM_SMEM);
    cudaFuncSetAttribute(mma_gemm<false, false>, cudaFuncAttributeMaxDynamicSharedMemorySize, GEMM_SMEM);
    cudaFuncSetAttribute(mma_gemm<true,  false>, cudaFuncAttributeMaxDynamicSharedMemorySize, GEMM_SMEM);
    cudaFuncSetAttribute(mma_gemm<false, true >, cudaFuncAttributeMaxDynamicSharedMemorySize, GEMM_SMEM);

    // 0) tf32-rounded operand prep
    {
        const int n4x = (NB * NL * NE) / 4;
        round_copy<<<(n4x + 255) / 256, 256>>>((const float4*)x, (float4*)xr, n4x);
        const int n4w = (2 * NE * NE) / 4;
        round_copy<<<(n4w + 255) / 256, 256>>>((const float4*)w, (float4*)wr, n4w);
        transpose_round<<<dim3(NE / 32, NL / 32, NB), dim3(32, 8)>>>(x, xT, NL, NE);
        transpose_round<<<dim3(NE / 32, NE / 32, 1), dim3(32, 8)>>>(Wg, WgT, NE, NE);
    }

    // 1) QK = xr @ wr^T + bias      [16384 x 512], K=256
    mma_gemm<true, true><<<dim3(4, 128, 1), 256, GEMM_SMEM>>>(
        xr, NE, 0, 0, 0,
        wr, NE, 0, 0, 0,
        QK, 2 * NE, 0,
        1, NE / 32, 1.f, bia);

    // 2) S[b*4+h] = 0.125 * q_h @ k_h^T    [2048 x 2048] x32, K=64
    mma_gemm<false, false><<<dim3(16, 16, NB * NH), 256, GEMM_SMEM>>>(
        QK, 2 * NE, NL, ND, 0,
        QK, 2 * NE, NL, ND, NE,
        S, NL, (long)NL * NL,
        NH, ND / 32, 0.125f, nullptr);

    // 3) Bm[b,i,:] = mean_h softmax(S[b,h,i,:])   (tf32-rounded)
    softmax_mean_kernel<<<NB * NL, 256>>>(S, Bm);

    // 4) AG[b] = Bm[b] @ xT[b]^T    [2048 x 256] x8, K=2048
    mma_gemm<true, false><<<dim3(2, 16, NB), 256, GEMM_SMEM>>>(
        Bm, NL, NL, 0, 0,
        xT, NL, NE, 0, 0,
        AG, NE, (long)NL * NE,
        1, NL / 32, 1.f, nullptr);

    // 5) out = AG @ WgT^T + Bg      [16384 x 256], K=256
    mma_gemm<false, true><<<dim3(2, 128, 1), 256, GEMM_SMEM>>>(
        AG, NE, 0, 0, 0,
        WgT, NE, 0, 0, 0,
        out, NE, 0,
        1, NE / 32, 1.f, Bg);
}